// round 8
// baseline (speedup 1.0000x reference)
#include <cuda_runtime.h>
#include <cuda_bf16.h>
#include <math_constants.h>

// Problem constants (fixed shapes for this problem)
#define NNODES 100000
#define NEDGES 1600000
#define TOTE   (NEDGES + NNODES)
#define HDIM   128
#define NG     64
#define SCAN_CHUNK 1024
#define NSCANBLK ((NNODES + SCAN_CHUNK - 1) / SCAN_CHUNK)
#define GEMM_BLOCKS ((NNODES + 127) / 128)
#define ZERO_BLOCKS ((NNODES + 255) / 256)

// ---------------- scratch (device globals; no allocation allowed) -----------
__device__ __align__(16) float g_h[(size_t)NNODES * HDIM];     // x @ W
__device__ __align__(16) float g_gnn[(size_t)NNODES * HDIM];   // silu(agg+bias)
__device__ float g_as[NNODES];
__device__ float g_ad[NNODES];
__device__ int   g_deg[NNODES];
__device__ int   g_off[NNODES + 1];
__device__ int   g_cursor[NNODES];
__device__ int   g_esrc[TOTE];
__device__ float g_ew[TOTE];
__device__ float g_pooled[NG * HDIM];
__device__ float g_cnt[NG];

// ---------------- helpers ----------------------------------------------------
__device__ __forceinline__ void edge_sd(const int* __restrict__ ei, int e, int E,
                                        int& s, int& d) {
    if (e < E) { s = ei[e]; d = ei[E + e]; }
    else       { s = e - E; d = s; }        // self loops appended
}

// ---------------- 1) GEMM + att epilogue, with zeroing blocks fused ----------
// Zero blocks touch only g_deg/g_pooled/g_cnt; gemm blocks touch g_h/g_as/g_ad.
// No shared state, no cross-block barriers -> safe in one launch.
__global__ __launch_bounds__(256, 2) void gemm_att_zero(
    const float* __restrict__ x, const float* __restrict__ W,
    const float* __restrict__ att_src, const float* __restrict__ att_dst, int M)
{
    if (blockIdx.x >= GEMM_BLOCKS) {
        int i = (blockIdx.x - GEMM_BLOCKS) * blockDim.x + threadIdx.x;
        if (i < NNODES) g_deg[i] = 0;
        if (i < NG * HDIM) g_pooled[i] = 0.f;
        if (i < NG) g_cnt[i] = 0.f;
        return;
    }

    __shared__ __align__(16) float Xs[32][132];   // transposed: Xs[k][row]
    __shared__ __align__(16) float Ws[32][132];   // Ws[k][col]

    const int tid = threadIdx.x;
    const int tx  = tid & 15;        // col group
    const int ty  = tid >> 4;        // row group
    const int m0  = blockIdx.x * 128;

    float acc[8][8];
    #pragma unroll
    for (int r = 0; r < 8; r++)
        #pragma unroll
        for (int c = 0; c < 8; c++) acc[r][c] = 0.f;

    for (int k0 = 0; k0 < HDIM; k0 += 32) {
        #pragma unroll
        for (int i = 0; i < 4; i++) {
            int f   = tid + i * 256;           // 0..1023 float4 index
            int row = f >> 3;
            int k4  = (f & 7) * 4;
            float4 v = make_float4(0.f, 0.f, 0.f, 0.f);
            int gr = m0 + row;
            if (gr < M) v = *(const float4*)&x[(size_t)gr * HDIM + k0 + k4];
            Xs[k4 + 0][row] = v.x;
            Xs[k4 + 1][row] = v.y;
            Xs[k4 + 2][row] = v.z;
            Xs[k4 + 3][row] = v.w;
        }
        #pragma unroll
        for (int i = 0; i < 4; i++) {
            int f  = tid + i * 256;
            int kr = f >> 5;
            int c4 = (f & 31) * 4;
            *(float4*)&Ws[kr][c4] = *(const float4*)&W[(size_t)(k0 + kr) * HDIM + c4];
        }
        __syncthreads();

        #pragma unroll
        for (int kk = 0; kk < 32; kk++) {
            float a[8], b[8];
            *(float4*)&a[0] = *(const float4*)&Xs[kk][ty * 8];
            *(float4*)&a[4] = *(const float4*)&Xs[kk][ty * 8 + 4];
            *(float4*)&b[0] = *(const float4*)&Ws[kk][tx * 8];
            *(float4*)&b[4] = *(const float4*)&Ws[kk][tx * 8 + 4];
            #pragma unroll
            for (int r = 0; r < 8; r++)
                #pragma unroll
                for (int c = 0; c < 8; c++)
                    acc[r][c] += a[r] * b[c];
        }
        __syncthreads();
    }

    float asv[8], adv[8];
    #pragma unroll
    for (int c = 0; c < 8; c++) {
        asv[c] = __ldg(&att_src[tx * 8 + c]);
        adv[c] = __ldg(&att_dst[tx * 8 + c]);
    }

    #pragma unroll
    for (int r = 0; r < 8; r++) {
        int gr = m0 + ty * 8 + r;
        if (gr < M) {
            float4 o0 = make_float4(acc[r][0], acc[r][1], acc[r][2], acc[r][3]);
            float4 o1 = make_float4(acc[r][4], acc[r][5], acc[r][6], acc[r][7]);
            *(float4*)&g_h[(size_t)gr * HDIM + tx * 8]     = o0;
            *(float4*)&g_h[(size_t)gr * HDIM + tx * 8 + 4] = o1;
        }
        float sv = 0.f, dv = 0.f;
        #pragma unroll
        for (int c = 0; c < 8; c++) {
            sv += acc[r][c] * asv[c];
            dv += acc[r][c] * adv[c];
        }
        #pragma unroll
        for (int o = 8; o; o >>= 1) {
            sv += __shfl_down_sync(0xffffffffu, sv, o, 16);
            dv += __shfl_down_sync(0xffffffffu, dv, o, 16);
        }
        if (tx == 0 && gr < M) { g_as[gr] = sv; g_ad[gr] = dv; }
    }
}

// ---------------- 2) degree count --------------------------------------------
__global__ void count_deg(const int* __restrict__ ei, int E, int n)
{
    int e = blockIdx.x * blockDim.x + threadIdx.x;
    if (e >= E + n) return;
    int s, d;
    edge_sd(ei, e, E, s, d);
    atomicAdd(&g_deg[d], 1);
}

// ---------------- 3) single-kernel scan, zero inter-block communication ------
// Each of the 98 blocks independently re-reduces g_deg[0 .. bid*1024) for its
// carry (~20MB total extra L2-hot reads ~ 3us), then scans its own chunk.
__global__ __launch_bounds__(1024) void scan_single(int n)
{
    __shared__ int wsum[32];
    __shared__ int csum[32];
    __shared__ int carry_s;
    const int tid = threadIdx.x, lane = tid & 31, w = tid >> 5;
    const int bid = blockIdx.x;

    // carry = sum of all deg entries in preceding chunks
    int c = 0;
    const int limit = bid * SCAN_CHUNK;
    for (int j = tid; j < limit; j += 1024) c += g_deg[j];
    #pragma unroll
    for (int o = 16; o; o >>= 1) c += __shfl_down_sync(0xffffffffu, c, o);
    if (lane == 0) csum[w] = c;
    __syncthreads();
    if (w == 0) {
        int cc = csum[lane];
        #pragma unroll
        for (int o = 16; o; o >>= 1) cc += __shfl_down_sync(0xffffffffu, cc, o);
        if (lane == 0) carry_s = cc;
    }

    // block-local inclusive scan of own chunk
    int i = bid * SCAN_CHUNK + tid;
    int v = (i < n) ? g_deg[i] : 0;
    int s = v;
    #pragma unroll
    for (int o = 1; o < 32; o <<= 1) {
        int t = __shfl_up_sync(0xffffffffu, s, o);
        if (lane >= o) s += t;
    }
    if (lane == 31) wsum[w] = s;
    __syncthreads();
    if (w == 0) {
        int ws = wsum[lane];
        #pragma unroll
        for (int o = 1; o < 32; o <<= 1) {
            int t = __shfl_up_sync(0xffffffffu, ws, o);
            if (lane >= o) ws += t;
        }
        wsum[lane] = ws;
    }
    __syncthreads();
    int prefix = (w > 0) ? wsum[w - 1] : 0;
    int excl = carry_s + prefix + s - v;
    if (i < n) { g_off[i] = excl; g_cursor[i] = excl; }
    if (bid == 0 && tid == 0) g_off[n] = TOTE;
}

// ---------------- 4) scatter edges + precompute softmax weights --------------
// (4th kernel launch -> profiled by the harness ncu pass)
__global__ void scatter_w(const int* __restrict__ ei, int E, int n)
{
    int e = blockIdx.x * blockDim.x + threadIdx.x;
    if (e >= E + n) return;
    int s, d;
    edge_sd(ei, e, E, s, d);
    float v = g_as[s] + g_ad[d];
    v = (v > 0.f) ? v : 0.2f * v;
    float wgt = __expf(v);               // no-max softmax: logits are small
    int pos = atomicAdd(&g_cursor[d], 1);
    g_esrc[pos] = s;
    g_ew[pos]   = wgt;
}

// ---------------- 5) warp-per-node streaming gather --------------------------
__global__ __launch_bounds__(256) void node_gather(
    const float* __restrict__ bias, int n)
{
    int warp = (blockIdx.x * blockDim.x + threadIdx.x) >> 5;
    int lane = threadIdx.x & 31;
    if (warp >= n) return;

    const int s0 = g_off[warp];
    const int s1 = g_off[warp + 1];
    const size_t col = lane * 4;

    float4 acc0 = make_float4(0.f, 0.f, 0.f, 0.f);
    float4 acc1 = make_float4(0.f, 0.f, 0.f, 0.f);
    float den = 0.f;

    for (int base = s0; base < s1; base += 32) {
        int i = base + lane;
        int src_l = 0;
        float e_l = 0.f;
        if (i < s1) {
            src_l = __ldg(&g_esrc[i]);
            e_l   = __ldg(&g_ew[i]);
        }
        den += e_l;

        int cnt = min(32, s1 - base);
        int t = 0;
        for (; t + 4 <= cnt; t += 4) {
            int sa = __shfl_sync(0xffffffffu, src_l, t);
            int sb = __shfl_sync(0xffffffffu, src_l, t + 1);
            int sc = __shfl_sync(0xffffffffu, src_l, t + 2);
            int sd = __shfl_sync(0xffffffffu, src_l, t + 3);
            float wa = __shfl_sync(0xffffffffu, e_l, t);
            float wb = __shfl_sync(0xffffffffu, e_l, t + 1);
            float wc = __shfl_sync(0xffffffffu, e_l, t + 2);
            float wd = __shfl_sync(0xffffffffu, e_l, t + 3);
            float4 ha = *(const float4*)&g_h[(size_t)sa * HDIM + col];
            float4 hb = *(const float4*)&g_h[(size_t)sb * HDIM + col];
            float4 hc = *(const float4*)&g_h[(size_t)sc * HDIM + col];
            float4 hd = *(const float4*)&g_h[(size_t)sd * HDIM + col];
            acc0.x += wa * ha.x; acc0.y += wa * ha.y; acc0.z += wa * ha.z; acc0.w += wa * ha.w;
            acc1.x += wb * hb.x; acc1.y += wb * hb.y; acc1.z += wb * hb.z; acc1.w += wb * hb.w;
            acc0.x += wc * hc.x; acc0.y += wc * hc.y; acc0.z += wc * hc.z; acc0.w += wc * hc.w;
            acc1.x += wd * hd.x; acc1.y += wd * hd.y; acc1.z += wd * hd.z; acc1.w += wd * hd.w;
        }
        for (; t < cnt; t++) {
            int ss = __shfl_sync(0xffffffffu, src_l, t);
            float ww = __shfl_sync(0xffffffffu, e_l, t);
            float4 hv = *(const float4*)&g_h[(size_t)ss * HDIM + col];
            acc0.x += ww * hv.x; acc0.y += ww * hv.y; acc0.z += ww * hv.z; acc0.w += ww * hv.w;
        }
    }

    #pragma unroll
    for (int o = 16; o; o >>= 1) den += __shfl_xor_sync(0xffffffffu, den, o);
    const float inv = 1.0f / den;   // self-loop guarantees den > 0

    float4 b4 = *(const float4*)&bias[col];
    float x0 = (acc0.x + acc1.x) * inv + b4.x;
    float x1 = (acc0.y + acc1.y) * inv + b4.y;
    float x2 = (acc0.z + acc1.z) * inv + b4.z;
    float x3 = (acc0.w + acc1.w) * inv + b4.w;
    float4 g;
    g.x = x0 / (1.f + __expf(-x0));
    g.y = x1 / (1.f + __expf(-x1));
    g.z = x2 / (1.f + __expf(-x2));
    g.w = x3 / (1.f + __expf(-x3));
    *(float4*)&g_gnn[(size_t)warp * HDIM + col] = g;
}

// ---------------- 6) global mean pool (batch is sorted) ----------------------
__global__ void pool_kernel(const int* __restrict__ batch, int n)
{
    const int CH = 512;
    int j  = threadIdx.x;             // column
    int i0 = blockIdx.x * CH;
    float local = 0.f;
    float lcnt  = 0.f;
    int curg = -1;
    for (int t = 0; t < CH; t++) {
        int i = i0 + t;
        if (i >= n) break;
        int gid = batch[i];
        if (gid != curg) {
            if (curg >= 0) {
                atomicAdd(&g_pooled[curg * HDIM + j], local);
                if (j == 0) atomicAdd(&g_cnt[curg], lcnt);
            }
            curg = gid; local = 0.f; lcnt = 0.f;
        }
        local += g_gnn[(size_t)i * HDIM + j];
        lcnt  += 1.f;
    }
    if (curg >= 0) {
        atomicAdd(&g_pooled[curg * HDIM + j], local);
        if (j == 0) atomicAdd(&g_cnt[curg], lcnt);
    }
}

// ---------------- 7) final head ----------------------------------------------
__global__ void final_kernel(const float* __restrict__ fin_w,
                             const float* __restrict__ fin_b,
                             float* __restrict__ out)
{
    int gidx = blockIdx.x;
    int t = threadIdx.x;             // 128 threads
    __shared__ float red[4];
    float inv = 1.f / fmaxf(g_cnt[gidx], 1.f);
    float p = g_pooled[gidx * HDIM + t] * inv * fin_w[t];
    #pragma unroll
    for (int o = 16; o; o >>= 1) p += __shfl_down_sync(0xffffffffu, p, o);
    if ((t & 31) == 0) red[t >> 5] = p;
    __syncthreads();
    if (t == 0) out[gidx] = red[0] + red[1] + red[2] + red[3] + fin_b[0];
}

// ---------------- launch ------------------------------------------------------
// ncu captures the 4th kernel launch -> scatter_w is profiled this round.
extern "C" void kernel_launch(void* const* d_in, const int* in_sizes, int n_in,
                              void* d_out, int out_size)
{
    const float* x       = (const float*)d_in[0];
    const int*   ei      = (const int*)  d_in[1];
    const int*   batch   = (const int*)  d_in[2];
    const float* W       = (const float*)d_in[3];
    const float* att_src = (const float*)d_in[4];
    const float* att_dst = (const float*)d_in[5];
    const float* bias    = (const float*)d_in[6];
    const float* fin_w   = (const float*)d_in[7];
    const float* fin_b   = (const float*)d_in[8];
    float* out = (float*)d_out;

    const int n   = in_sizes[0] / HDIM;   // 100000
    const int E   = in_sizes[1] / 2;      // 1600000
    const int tot = E + n;

    // 1: GEMM + attention logits, with scratch zeroing fused into extra blocks
    gemm_att_zero<<<GEMM_BLOCKS + ZERO_BLOCKS, 256>>>(x, W, att_src, att_dst, n);
    // 2: degree count
    int eblocks = (tot + 255) / 256;
    count_deg<<<eblocks, 256>>>(ei, E, n);
    // 3: single-kernel exclusive scan (communication-free)
    scan_single<<<NSCANBLK, 1024>>>(n);
    // 4: scatter + precompute softmax weights  (PROFILED)
    scatter_w<<<eblocks, 256>>>(ei, E, n);
    // 5: streaming aggregation + silu
    int wblocks = (n * 32 + 255) / 256;
    node_gather<<<wblocks, 256>>>(bias, n);
    // 6-7: pooling + head
    pool_kernel<<<(n + 511) / 512, 128>>>(batch, n);
    final_kernel<<<NG, 128>>>(fin_w, fin_b, out);
}

// round 9
// speedup vs baseline: 1.0090x; 1.0090x over previous
#include <cuda_runtime.h>
#include <cuda_bf16.h>
#include <math_constants.h>

// Problem constants (fixed shapes for this problem)
#define NNODES 100000
#define NEDGES 1600000
#define TOTE   (NEDGES + NNODES)
#define HDIM   128
#define NG     64
#define SCAN_CHUNK 1024
#define NSCANBLK ((NNODES + SCAN_CHUNK - 1) / SCAN_CHUNK)
#define GEMM_BLOCKS ((NNODES + 127) / 128)
#define COUNT_BLOCKS ((TOTE + 255) / 256)

// ---------------- scratch (device globals; zero-initialized at load) --------
// g_deg / g_pooled / g_cnt are re-zeroed by tail_zero at the END of every
// launch, so each launch (and each graph replay) starts from zeros.
__device__ __align__(16) float g_h[(size_t)NNODES * HDIM];     // x @ W
__device__ __align__(16) float g_gnn[(size_t)NNODES * HDIM];   // silu(agg+bias)
__device__ float g_as[NNODES];
__device__ float g_ad[NNODES];
__device__ int   g_deg[NNODES];
__device__ int   g_off[NNODES + 1];
__device__ int   g_cursor[NNODES];
__device__ int   g_esrc[TOTE];
__device__ float g_ew[TOTE];
__device__ float g_pooled[NG * HDIM];
__device__ float g_cnt[NG];

// ---------------- helpers ----------------------------------------------------
__device__ __forceinline__ void edge_sd(const int* __restrict__ ei, int e, int E,
                                        int& s, int& d) {
    if (e < E) { s = ei[e]; d = ei[E + e]; }
    else       { s = e - E; d = s; }        // self loops appended
}

// ---------------- 1) GEMM + att epilogue, degree-count blocks fused ----------
// Count blocks only histogram into pre-zeroed g_deg (no dependency on gemm
// blocks within this launch).
__global__ __launch_bounds__(256, 2) void gemm_att_count(
    const float* __restrict__ x, const float* __restrict__ W,
    const float* __restrict__ att_src, const float* __restrict__ att_dst,
    const int* __restrict__ ei, int E, int M)
{
    if (blockIdx.x >= GEMM_BLOCKS) {
        int e = (blockIdx.x - GEMM_BLOCKS) * blockDim.x + threadIdx.x;
        if (e < E + M) {
            int s, d;
            edge_sd(ei, e, E, s, d);
            atomicAdd(&g_deg[d], 1);
        }
        return;
    }

    __shared__ __align__(16) float Xs[32][132];   // transposed: Xs[k][row]
    __shared__ __align__(16) float Ws[32][132];   // Ws[k][col]

    const int tid = threadIdx.x;
    const int tx  = tid & 15;        // col group
    const int ty  = tid >> 4;        // row group
    const int m0  = blockIdx.x * 128;

    float acc[8][8];
    #pragma unroll
    for (int r = 0; r < 8; r++)
        #pragma unroll
        for (int c = 0; c < 8; c++) acc[r][c] = 0.f;

    for (int k0 = 0; k0 < HDIM; k0 += 32) {
        #pragma unroll
        for (int i = 0; i < 4; i++) {
            int f   = tid + i * 256;           // 0..1023 float4 index
            int row = f >> 3;
            int k4  = (f & 7) * 4;
            float4 v = make_float4(0.f, 0.f, 0.f, 0.f);
            int gr = m0 + row;
            if (gr < M) v = *(const float4*)&x[(size_t)gr * HDIM + k0 + k4];
            Xs[k4 + 0][row] = v.x;
            Xs[k4 + 1][row] = v.y;
            Xs[k4 + 2][row] = v.z;
            Xs[k4 + 3][row] = v.w;
        }
        #pragma unroll
        for (int i = 0; i < 4; i++) {
            int f  = tid + i * 256;
            int kr = f >> 5;
            int c4 = (f & 31) * 4;
            *(float4*)&Ws[kr][c4] = *(const float4*)&W[(size_t)(k0 + kr) * HDIM + c4];
        }
        __syncthreads();

        #pragma unroll
        for (int kk = 0; kk < 32; kk++) {
            float a[8], b[8];
            *(float4*)&a[0] = *(const float4*)&Xs[kk][ty * 8];
            *(float4*)&a[4] = *(const float4*)&Xs[kk][ty * 8 + 4];
            *(float4*)&b[0] = *(const float4*)&Ws[kk][tx * 8];
            *(float4*)&b[4] = *(const float4*)&Ws[kk][tx * 8 + 4];
            #pragma unroll
            for (int r = 0; r < 8; r++)
                #pragma unroll
                for (int c = 0; c < 8; c++)
                    acc[r][c] += a[r] * b[c];
        }
        __syncthreads();
    }

    float asv[8], adv[8];
    #pragma unroll
    for (int c = 0; c < 8; c++) {
        asv[c] = __ldg(&att_src[tx * 8 + c]);
        adv[c] = __ldg(&att_dst[tx * 8 + c]);
    }

    #pragma unroll
    for (int r = 0; r < 8; r++) {
        int gr = m0 + ty * 8 + r;
        if (gr < M) {
            float4 o0 = make_float4(acc[r][0], acc[r][1], acc[r][2], acc[r][3]);
            float4 o1 = make_float4(acc[r][4], acc[r][5], acc[r][6], acc[r][7]);
            *(float4*)&g_h[(size_t)gr * HDIM + tx * 8]     = o0;
            *(float4*)&g_h[(size_t)gr * HDIM + tx * 8 + 4] = o1;
        }
        float sv = 0.f, dv = 0.f;
        #pragma unroll
        for (int c = 0; c < 8; c++) {
            sv += acc[r][c] * asv[c];
            dv += acc[r][c] * adv[c];
        }
        #pragma unroll
        for (int o = 8; o; o >>= 1) {
            sv += __shfl_down_sync(0xffffffffu, sv, o, 16);
            dv += __shfl_down_sync(0xffffffffu, dv, o, 16);
        }
        if (tx == 0 && gr < M) { g_as[gr] = sv; g_ad[gr] = dv; }
    }
}

// ---------------- 2) single-kernel scan, zero inter-block communication ------
__global__ __launch_bounds__(1024) void scan_single(int n)
{
    __shared__ int wsum[32];
    __shared__ int csum[32];
    __shared__ int carry_s;
    const int tid = threadIdx.x, lane = tid & 31, w = tid >> 5;
    const int bid = blockIdx.x;

    // carry = sum of all deg entries in preceding chunks
    int c = 0;
    const int limit = bid * SCAN_CHUNK;
    for (int j = tid; j < limit; j += 1024) c += g_deg[j];
    #pragma unroll
    for (int o = 16; o; o >>= 1) c += __shfl_down_sync(0xffffffffu, c, o);
    if (lane == 0) csum[w] = c;
    __syncthreads();
    if (w == 0) {
        int cc = csum[lane];
        #pragma unroll
        for (int o = 16; o; o >>= 1) cc += __shfl_down_sync(0xffffffffu, cc, o);
        if (lane == 0) carry_s = cc;
    }

    // block-local inclusive scan of own chunk
    int i = bid * SCAN_CHUNK + tid;
    int v = (i < n) ? g_deg[i] : 0;
    int s = v;
    #pragma unroll
    for (int o = 1; o < 32; o <<= 1) {
        int t = __shfl_up_sync(0xffffffffu, s, o);
        if (lane >= o) s += t;
    }
    if (lane == 31) wsum[w] = s;
    __syncthreads();
    if (w == 0) {
        int ws = wsum[lane];
        #pragma unroll
        for (int o = 1; o < 32; o <<= 1) {
            int t = __shfl_up_sync(0xffffffffu, ws, o);
            if (lane >= o) ws += t;
        }
        wsum[lane] = ws;
    }
    __syncthreads();
    int prefix = (w > 0) ? wsum[w - 1] : 0;
    int excl = carry_s + prefix + s - v;
    if (i < n) { g_off[i] = excl; g_cursor[i] = excl; }
    if (bid == 0 && tid == 0) g_off[n] = TOTE;
}

// ---------------- 3) scatter edges + precompute softmax weights --------------
__global__ void scatter_w(const int* __restrict__ ei, int E, int n)
{
    int e = blockIdx.x * blockDim.x + threadIdx.x;
    if (e >= E + n) return;
    int s, d;
    edge_sd(ei, e, E, s, d);
    float v = g_as[s] + g_ad[d];
    v = (v > 0.f) ? v : 0.2f * v;
    float wgt = __expf(v);               // no-max softmax: logits are small
    int pos = atomicAdd(&g_cursor[d], 1);
    g_esrc[pos] = s;
    g_ew[pos]   = wgt;
}

// ---------------- 4) shuffle-free parallel gather (PROFILED) ------------------
// warp = node; lanes split into 4 edge-slots x 8 column-slots.
// Each group processes 4 edges simultaneously: 4 independent LDG.128 per
// q-quarter, no shuffles in the hot loop, groups fully independent -> MLP.
__global__ __launch_bounds__(256) void node_gather(
    const float* __restrict__ bias, int n)
{
    int warp = (blockIdx.x * blockDim.x + threadIdx.x) >> 5;
    int lane = threadIdx.x & 31;
    if (warp >= n) return;

    const int s0 = g_off[warp];
    const int s1 = g_off[warp + 1];
    const int eslot = lane >> 3;     // 0..3: which edge of the group
    const int cslot = lane & 7;      // 0..7: which 16B of the column quarter

    float4 acc[4];
    #pragma unroll
    for (int q = 0; q < 4; q++) acc[q] = make_float4(0.f, 0.f, 0.f, 0.f);
    float den_l = 0.f;

    for (int base = s0; base < s1; base += 4) {
        int i = base + eslot;
        int src;
        float wt;
        if (i < s1) {
            src = __ldg(&g_esrc[i]);
            wt  = __ldg(&g_ew[i]);
        } else {
            src = warp;              // valid row, zero weight
            wt  = 0.f;
        }
        den_l += wt;
        const float* row = &g_h[(size_t)src * HDIM + cslot * 4];
        #pragma unroll
        for (int q = 0; q < 4; q++) {
            float4 hv = *(const float4*)&row[q * 32];
            acc[q].x += wt * hv.x;
            acc[q].y += wt * hv.y;
            acc[q].z += wt * hv.z;
            acc[q].w += wt * hv.w;
        }
    }

    // each edge's weight was accumulated by 8 lanes -> den = warp_sum / 8
    float den = den_l;
    #pragma unroll
    for (int o = 16; o; o >>= 1) den += __shfl_xor_sync(0xffffffffu, den, o);
    den *= 0.125f;
    const float inv = 1.0f / den;    // self-loop guarantees den > 0

    // reduce accumulators across the 4 edge-slots (lane bits 3 and 4)
    #pragma unroll
    for (int q = 0; q < 4; q++) {
        acc[q].x += __shfl_xor_sync(0xffffffffu, acc[q].x, 8);
        acc[q].y += __shfl_xor_sync(0xffffffffu, acc[q].y, 8);
        acc[q].z += __shfl_xor_sync(0xffffffffu, acc[q].z, 8);
        acc[q].w += __shfl_xor_sync(0xffffffffu, acc[q].w, 8);
        acc[q].x += __shfl_xor_sync(0xffffffffu, acc[q].x, 16);
        acc[q].y += __shfl_xor_sync(0xffffffffu, acc[q].y, 16);
        acc[q].z += __shfl_xor_sync(0xffffffffu, acc[q].z, 16);
        acc[q].w += __shfl_xor_sync(0xffffffffu, acc[q].w, 16);
    }

    if (lane < 8) {
        const float4* bias4 = (const float4*)bias;
        #pragma unroll
        for (int q = 0; q < 4; q++) {
            float4 b4 = __ldg(&bias4[q * 8 + lane]);
            float x0 = acc[q].x * inv + b4.x;
            float x1 = acc[q].y * inv + b4.y;
            float x2 = acc[q].z * inv + b4.z;
            float x3 = acc[q].w * inv + b4.w;
            float4 g;
            g.x = x0 / (1.f + __expf(-x0));
            g.y = x1 / (1.f + __expf(-x1));
            g.z = x2 / (1.f + __expf(-x2));
            g.w = x3 / (1.f + __expf(-x3));
            *(float4*)&g_gnn[(size_t)warp * HDIM + q * 32 + lane * 4] = g;
        }
    }
}

// ---------------- 5) global mean pool (batch is sorted) ----------------------
__global__ void pool_kernel(const int* __restrict__ batch, int n)
{
    const int CH = 512;
    int j  = threadIdx.x;             // column
    int i0 = blockIdx.x * CH;
    float local = 0.f;
    float lcnt  = 0.f;
    int curg = -1;
    for (int t = 0; t < CH; t++) {
        int i = i0 + t;
        if (i >= n) break;
        int gid = batch[i];
        if (gid != curg) {
            if (curg >= 0) {
                atomicAdd(&g_pooled[curg * HDIM + j], local);
                if (j == 0) atomicAdd(&g_cnt[curg], lcnt);
            }
            curg = gid; local = 0.f; lcnt = 0.f;
        }
        local += g_gnn[(size_t)i * HDIM + j];
        lcnt  += 1.f;
    }
    if (curg >= 0) {
        atomicAdd(&g_pooled[curg * HDIM + j], local);
        if (j == 0) atomicAdd(&g_cnt[curg], lcnt);
    }
}

// ---------------- 6) final head ----------------------------------------------
__global__ void final_kernel(const float* __restrict__ fin_w,
                             const float* __restrict__ fin_b,
                             float* __restrict__ out)
{
    int gidx = blockIdx.x;
    int t = threadIdx.x;             // 128 threads
    __shared__ float red[4];
    float inv = 1.f / fmaxf(g_cnt[gidx], 1.f);
    float p = g_pooled[gidx * HDIM + t] * inv * fin_w[t];
    #pragma unroll
    for (int o = 16; o; o >>= 1) p += __shfl_down_sync(0xffffffffu, p, o);
    if ((t & 31) == 0) red[t >> 5] = p;
    __syncthreads();
    if (t == 0) out[gidx] = red[0] + red[1] + red[2] + red[3] + fin_b[0];
}

// ---------------- 7) tail: re-zero scratch for the next launch/replay --------
__global__ void tail_zero(int n)
{
    int i = blockIdx.x * blockDim.x + threadIdx.x;
    if (i < n) g_deg[i] = 0;
    if (i < NG * HDIM) g_pooled[i] = 0.f;
    if (i < NG) g_cnt[i] = 0.f;
}

// ---------------- launch ------------------------------------------------------
// ncu captures the 4th kernel launch -> node_gather is profiled this round.
extern "C" void kernel_launch(void* const* d_in, const int* in_sizes, int n_in,
                              void* d_out, int out_size)
{
    const float* x       = (const float*)d_in[0];
    const int*   ei      = (const int*)  d_in[1];
    const int*   batch   = (const int*)  d_in[2];
    const float* W       = (const float*)d_in[3];
    const float* att_src = (const float*)d_in[4];
    const float* att_dst = (const float*)d_in[5];
    const float* bias    = (const float*)d_in[6];
    const float* fin_w   = (const float*)d_in[7];
    const float* fin_b   = (const float*)d_in[8];
    float* out = (float*)d_out;

    const int n   = in_sizes[0] / HDIM;   // 100000
    const int E   = in_sizes[1] / 2;      // 1600000
    const int tot = E + n;

    // 1: GEMM + attention logits, with degree counting fused into extra blocks
    gemm_att_count<<<GEMM_BLOCKS + COUNT_BLOCKS, 256>>>(x, W, att_src, att_dst,
                                                        ei, E, n);
    // 2: exclusive scan (communication-free single kernel)
    scan_single<<<NSCANBLK, 1024>>>(n);
    // 3: scatter + precompute softmax weights
    int eblocks = (tot + 255) / 256;
    scatter_w<<<eblocks, 256>>>(ei, E, n);
    // 4: aggregation + silu (PROFILED)
    int wblocks = (n * 32 + 255) / 256;
    node_gather<<<wblocks, 256>>>(bias, n);
    // 5-6: pooling + head
    pool_kernel<<<(n + 511) / 512, 128>>>(batch, n);
    final_kernel<<<NG, 128>>>(fin_w, fin_b, out);
    // 7: re-zero scratch for the next launch / graph replay
    tail_zero<<<(n + 255) / 256, 256>>>(n);
}

// round 10
// speedup vs baseline: 1.8807x; 1.8639x over previous
#include <cuda_runtime.h>
#include <cuda_bf16.h>
#include <math_constants.h>

// Problem constants (fixed shapes for this problem)
#define NNODES 100000
#define NEDGES 1600000
#define TOTE   (NEDGES + NNODES)
#define HDIM   128
#define NG     64
#define SCAN_CHUNK 1024
#define NSCANBLK ((NNODES + SCAN_CHUNK - 1) / SCAN_CHUNK)
#define GEMM_BLOCKS ((NNODES + 127) / 128)
#define COUNT_BLOCKS ((TOTE + 255) / 256)

// ---------------- scratch (device globals; zero-initialized at load) --------
// g_deg is re-zeroed by tail_zero at the END of every launch, so each launch
// (and each graph replay) starts from zeros.
__device__ __align__(16) float g_h[(size_t)NNODES * HDIM];     // x @ W
__device__ __align__(16) float g_gnn[(size_t)NNODES * HDIM];   // silu(agg+bias)
__device__ float g_as[NNODES];
__device__ float g_ad[NNODES];
__device__ int   g_deg[NNODES];
__device__ int   g_off[NNODES + 1];
__device__ int   g_cursor[NNODES];
__device__ int   g_esrc[TOTE];
__device__ float g_ew[TOTE];
__device__ int   g_roff[NG + 1];      // per-graph node ranges (batch is sorted)
__device__ float g_pooled[NG * HDIM]; // written directly (no atomics/zeroing)

// ---------------- helpers ----------------------------------------------------
__device__ __forceinline__ void edge_sd(const int* __restrict__ ei, int e, int E,
                                        int& s, int& d) {
    if (e < E) { s = ei[e]; d = ei[E + e]; }
    else       { s = e - E; d = s; }        // self loops appended
}

// ---------------- 1) GEMM + att epilogue, degree-count blocks fused ----------
__global__ __launch_bounds__(256, 2) void gemm_att_count(
    const float* __restrict__ x, const float* __restrict__ W,
    const float* __restrict__ att_src, const float* __restrict__ att_dst,
    const int* __restrict__ ei, int E, int M)
{
    if (blockIdx.x >= GEMM_BLOCKS) {
        int e = (blockIdx.x - GEMM_BLOCKS) * blockDim.x + threadIdx.x;
        if (e < E + M) {
            int s, d;
            edge_sd(ei, e, E, s, d);
            atomicAdd(&g_deg[d], 1);
        }
        return;
    }

    __shared__ __align__(16) float Xs[32][132];   // transposed: Xs[k][row]
    __shared__ __align__(16) float Ws[32][132];   // Ws[k][col]

    const int tid = threadIdx.x;
    const int tx  = tid & 15;        // col group
    const int ty  = tid >> 4;        // row group
    const int m0  = blockIdx.x * 128;

    float acc[8][8];
    #pragma unroll
    for (int r = 0; r < 8; r++)
        #pragma unroll
        for (int c = 0; c < 8; c++) acc[r][c] = 0.f;

    for (int k0 = 0; k0 < HDIM; k0 += 32) {
        #pragma unroll
        for (int i = 0; i < 4; i++) {
            int f   = tid + i * 256;           // 0..1023 float4 index
            int row = f >> 3;
            int k4  = (f & 7) * 4;
            float4 v = make_float4(0.f, 0.f, 0.f, 0.f);
            int gr = m0 + row;
            if (gr < M) v = *(const float4*)&x[(size_t)gr * HDIM + k0 + k4];
            Xs[k4 + 0][row] = v.x;
            Xs[k4 + 1][row] = v.y;
            Xs[k4 + 2][row] = v.z;
            Xs[k4 + 3][row] = v.w;
        }
        #pragma unroll
        for (int i = 0; i < 4; i++) {
            int f  = tid + i * 256;
            int kr = f >> 5;
            int c4 = (f & 31) * 4;
            *(float4*)&Ws[kr][c4] = *(const float4*)&W[(size_t)(k0 + kr) * HDIM + c4];
        }
        __syncthreads();

        #pragma unroll
        for (int kk = 0; kk < 32; kk++) {
            float a[8], b[8];
            *(float4*)&a[0] = *(const float4*)&Xs[kk][ty * 8];
            *(float4*)&a[4] = *(const float4*)&Xs[kk][ty * 8 + 4];
            *(float4*)&b[0] = *(const float4*)&Ws[kk][tx * 8];
            *(float4*)&b[4] = *(const float4*)&Ws[kk][tx * 8 + 4];
            #pragma unroll
            for (int r = 0; r < 8; r++)
                #pragma unroll
                for (int c = 0; c < 8; c++)
                    acc[r][c] += a[r] * b[c];
        }
        __syncthreads();
    }

    float asv[8], adv[8];
    #pragma unroll
    for (int c = 0; c < 8; c++) {
        asv[c] = __ldg(&att_src[tx * 8 + c]);
        adv[c] = __ldg(&att_dst[tx * 8 + c]);
    }

    #pragma unroll
    for (int r = 0; r < 8; r++) {
        int gr = m0 + ty * 8 + r;
        if (gr < M) {
            float4 o0 = make_float4(acc[r][0], acc[r][1], acc[r][2], acc[r][3]);
            float4 o1 = make_float4(acc[r][4], acc[r][5], acc[r][6], acc[r][7]);
            *(float4*)&g_h[(size_t)gr * HDIM + tx * 8]     = o0;
            *(float4*)&g_h[(size_t)gr * HDIM + tx * 8 + 4] = o1;
        }
        float sv = 0.f, dv = 0.f;
        #pragma unroll
        for (int c = 0; c < 8; c++) {
            sv += acc[r][c] * asv[c];
            dv += acc[r][c] * adv[c];
        }
        #pragma unroll
        for (int o = 8; o; o >>= 1) {
            sv += __shfl_down_sync(0xffffffffu, sv, o, 16);
            dv += __shfl_down_sync(0xffffffffu, dv, o, 16);
        }
        if (tx == 0 && gr < M) { g_as[gr] = sv; g_ad[gr] = dv; }
    }
}

// ---------------- 2) single-kernel scan, zero inter-block communication ------
__global__ __launch_bounds__(1024) void scan_single(int n)
{
    __shared__ int wsum[32];
    __shared__ int csum[32];
    __shared__ int carry_s;
    const int tid = threadIdx.x, lane = tid & 31, w = tid >> 5;
    const int bid = blockIdx.x;

    int c = 0;
    const int limit = bid * SCAN_CHUNK;
    for (int j = tid; j < limit; j += 1024) c += g_deg[j];
    #pragma unroll
    for (int o = 16; o; o >>= 1) c += __shfl_down_sync(0xffffffffu, c, o);
    if (lane == 0) csum[w] = c;
    __syncthreads();
    if (w == 0) {
        int cc = csum[lane];
        #pragma unroll
        for (int o = 16; o; o >>= 1) cc += __shfl_down_sync(0xffffffffu, cc, o);
        if (lane == 0) carry_s = cc;
    }

    int i = bid * SCAN_CHUNK + tid;
    int v = (i < n) ? g_deg[i] : 0;
    int s = v;
    #pragma unroll
    for (int o = 1; o < 32; o <<= 1) {
        int t = __shfl_up_sync(0xffffffffu, s, o);
        if (lane >= o) s += t;
    }
    if (lane == 31) wsum[w] = s;
    __syncthreads();
    if (w == 0) {
        int ws = wsum[lane];
        #pragma unroll
        for (int o = 1; o < 32; o <<= 1) {
            int t = __shfl_up_sync(0xffffffffu, ws, o);
            if (lane >= o) ws += t;
        }
        wsum[lane] = ws;
    }
    __syncthreads();
    int prefix = (w > 0) ? wsum[w - 1] : 0;
    int excl = carry_s + prefix + s - v;
    if (i < n) { g_off[i] = excl; g_cursor[i] = excl; }
    if (bid == 0 && tid == 0) g_off[n] = TOTE;
}

// ---------------- 3) scatter edges + precompute softmax weights --------------
__global__ void scatter_w(const int* __restrict__ ei, int E, int n)
{
    int e = blockIdx.x * blockDim.x + threadIdx.x;
    if (e >= E + n) return;
    int s, d;
    edge_sd(ei, e, E, s, d);
    float v = g_as[s] + g_ad[d];
    v = (v > 0.f) ? v : 0.2f * v;
    float wgt = __expf(v);               // no-max softmax: logits are small
    int pos = atomicAdd(&g_cursor[d], 1);
    g_esrc[pos] = s;
    g_ew[pos]   = wgt;
}

// ---------------- 4) shuffle-free parallel gather (PROFILED) ------------------
__global__ __launch_bounds__(256) void node_gather(
    const float* __restrict__ bias, int n)
{
    int warp = (blockIdx.x * blockDim.x + threadIdx.x) >> 5;
    int lane = threadIdx.x & 31;
    if (warp >= n) return;

    const int s0 = g_off[warp];
    const int s1 = g_off[warp + 1];
    const int eslot = lane >> 3;     // 0..3: which edge of the group
    const int cslot = lane & 7;      // 0..7: which 16B of the column quarter

    float4 acc[4];
    #pragma unroll
    for (int q = 0; q < 4; q++) acc[q] = make_float4(0.f, 0.f, 0.f, 0.f);
    float den_l = 0.f;

    for (int base = s0; base < s1; base += 4) {
        int i = base + eslot;
        int src;
        float wt;
        if (i < s1) {
            src = __ldg(&g_esrc[i]);
            wt  = __ldg(&g_ew[i]);
        } else {
            src = warp;              // valid row, zero weight
            wt  = 0.f;
        }
        den_l += wt;
        const float* row = &g_h[(size_t)src * HDIM + cslot * 4];
        #pragma unroll
        for (int q = 0; q < 4; q++) {
            float4 hv = *(const float4*)&row[q * 32];
            acc[q].x += wt * hv.x;
            acc[q].y += wt * hv.y;
            acc[q].z += wt * hv.z;
            acc[q].w += wt * hv.w;
        }
    }

    // each edge's weight was accumulated by 8 lanes -> den = warp_sum / 8
    float den = den_l;
    #pragma unroll
    for (int o = 16; o; o >>= 1) den += __shfl_xor_sync(0xffffffffu, den, o);
    den *= 0.125f;
    const float inv = 1.0f / den;    // self-loop guarantees den > 0

    #pragma unroll
    for (int q = 0; q < 4; q++) {
        acc[q].x += __shfl_xor_sync(0xffffffffu, acc[q].x, 8);
        acc[q].y += __shfl_xor_sync(0xffffffffu, acc[q].y, 8);
        acc[q].z += __shfl_xor_sync(0xffffffffu, acc[q].z, 8);
        acc[q].w += __shfl_xor_sync(0xffffffffu, acc[q].w, 8);
        acc[q].x += __shfl_xor_sync(0xffffffffu, acc[q].x, 16);
        acc[q].y += __shfl_xor_sync(0xffffffffu, acc[q].y, 16);
        acc[q].z += __shfl_xor_sync(0xffffffffu, acc[q].z, 16);
        acc[q].w += __shfl_xor_sync(0xffffffffu, acc[q].w, 16);
    }

    if (lane < 8) {
        const float4* bias4 = (const float4*)bias;
        #pragma unroll
        for (int q = 0; q < 4; q++) {
            float4 b4 = __ldg(&bias4[q * 8 + lane]);
            float x0 = acc[q].x * inv + b4.x;
            float x1 = acc[q].y * inv + b4.y;
            float x2 = acc[q].z * inv + b4.z;
            float x3 = acc[q].w * inv + b4.w;
            float4 g;
            g.x = x0 / (1.f + __expf(-x0));
            g.y = x1 / (1.f + __expf(-x1));
            g.z = x2 / (1.f + __expf(-x2));
            g.w = x3 / (1.f + __expf(-x3));
            *(float4*)&g_gnn[(size_t)warp * HDIM + q * 32 + lane * 4] = g;
        }
    }
}

// ---------------- 5) graph ranges (batch is sorted) --------------------------
// g_roff[g] = first node index with batch >= g; g_roff[NG] = n.
__global__ void graph_ranges(const int* __restrict__ batch, int n)
{
    int i = blockIdx.x * blockDim.x + threadIdx.x;
    if (i >= n) return;
    int b = batch[i];
    if (i == 0) {
        for (int g = 0; g <= b; g++) g_roff[g] = 0;
    } else {
        int pb = batch[i - 1];
        for (int g = pb + 1; g <= b; g++) g_roff[g] = i;
    }
    if (i == n - 1) {
        for (int g = b + 1; g <= NG; g++) g_roff[g] = n;
    }
}

// ---------------- 6) pool: branch-free streaming per (graph, col-tile) -------
// grid (NG, 4); block 128 = 4 rows x 32 cols. Unrolled 4x -> MLP>=4, full
// 128B coalesced lines, direct store, no atomics, no zeroing.
__global__ __launch_bounds__(128) void pool2(int n)
{
    const int g    = blockIdx.x;
    const int col  = blockIdx.y * 32 + (threadIdx.x & 31);
    const int trow = threadIdx.x >> 5;    // 0..3
    const int r0 = g_roff[g];
    const int r1 = g_roff[g + 1];

    float a0 = 0.f, a1 = 0.f, a2 = 0.f, a3 = 0.f;
    int r = r0 + trow;
    for (; r + 12 < r1; r += 16) {
        a0 += g_gnn[(size_t)(r)      * HDIM + col];
        a1 += g_gnn[(size_t)(r + 4)  * HDIM + col];
        a2 += g_gnn[(size_t)(r + 8)  * HDIM + col];
        a3 += g_gnn[(size_t)(r + 12) * HDIM + col];
    }
    for (; r < r1; r += 4) a0 += g_gnn[(size_t)r * HDIM + col];
    float acc = (a0 + a1) + (a2 + a3);

    __shared__ float sm[128];
    sm[threadIdx.x] = acc;
    __syncthreads();
    if (trow == 0) {
        int c = threadIdx.x;   // 0..31
        float s = sm[c] + sm[32 + c] + sm[64 + c] + sm[96 + c];
        g_pooled[g * HDIM + col] = s;
    }
}

// ---------------- 7) final head (count from ranges) --------------------------
__global__ void final_kernel(const float* __restrict__ fin_w,
                             const float* __restrict__ fin_b,
                             float* __restrict__ out)
{
    int gidx = blockIdx.x;
    int t = threadIdx.x;             // 128 threads
    __shared__ float red[4];
    float cnt = (float)(g_roff[gidx + 1] - g_roff[gidx]);
    float inv = 1.f / fmaxf(cnt, 1.f);
    float p = g_pooled[gidx * HDIM + t] * inv * fin_w[t];
    #pragma unroll
    for (int o = 16; o; o >>= 1) p += __shfl_down_sync(0xffffffffu, p, o);
    if ((t & 31) == 0) red[t >> 5] = p;
    __syncthreads();
    if (t == 0) out[gidx] = red[0] + red[1] + red[2] + red[3] + fin_b[0];
}

// ---------------- 8) tail: re-zero g_deg for the next launch/replay ----------
__global__ void tail_zero(int n)
{
    int i = blockIdx.x * blockDim.x + threadIdx.x;
    if (i < n) g_deg[i] = 0;
}

// ---------------- launch ------------------------------------------------------
// ncu captures the 4th kernel launch -> node_gather stays profiled.
extern "C" void kernel_launch(void* const* d_in, const int* in_sizes, int n_in,
                              void* d_out, int out_size)
{
    const float* x       = (const float*)d_in[0];
    const int*   ei      = (const int*)  d_in[1];
    const int*   batch   = (const int*)  d_in[2];
    const float* W       = (const float*)d_in[3];
    const float* att_src = (const float*)d_in[4];
    const float* att_dst = (const float*)d_in[5];
    const float* bias    = (const float*)d_in[6];
    const float* fin_w   = (const float*)d_in[7];
    const float* fin_b   = (const float*)d_in[8];
    float* out = (float*)d_out;

    const int n   = in_sizes[0] / HDIM;   // 100000
    const int E   = in_sizes[1] / 2;      // 1600000
    const int tot = E + n;

    // 1: GEMM + attention logits, degree counting fused into extra blocks
    gemm_att_count<<<GEMM_BLOCKS + COUNT_BLOCKS, 256>>>(x, W, att_src, att_dst,
                                                        ei, E, n);
    // 2: exclusive scan (communication-free single kernel)
    scan_single<<<NSCANBLK, 1024>>>(n);
    // 3: scatter + precompute softmax weights
    int eblocks = (tot + 255) / 256;
    scatter_w<<<eblocks, 256>>>(ei, E, n);
    // 4: aggregation + silu (PROFILED)
    int wblocks = (n * 32 + 255) / 256;
    node_gather<<<wblocks, 256>>>(bias, n);
    // 5: per-graph node ranges
    graph_ranges<<<(n + 255) / 256, 256>>>(batch, n);
    // 6: streaming mean-pool (sum; divide in final)
    pool2<<<dim3(NG, 4), 128>>>(n);
    // 7: head
    final_kernel<<<NG, 128>>>(fin_w, fin_b, out);
    // 8: re-zero degree histogram for the next launch / graph replay
    tail_zero<<<(n + 255) / 256, 256>>>(n);
}